// round 2
// baseline (speedup 1.0000x reference)
#include <cuda_runtime.h>

// Problem constants: B=4096, N=64, H=16, FALLBACK_SIZE=12
// grid:  (B,1,64,64) f32   hints: (B,2,64,16) f32
// w_g:   (1,64,64)   f32   w_h:   (2,64,16)   f32
// out:   scalar f32

static __global__ void zero_kernel(float* out) { out[0] = 0.0f; }

__global__ void __launch_bounds__(256) energy_kernel(
    const float* __restrict__ grid, const float* __restrict__ hints,
    const float* __restrict__ wg,   const float* __restrict__ wh,
    float* __restrict__ out)
{
    __shared__ float hsum[128];       // [0..63] row targets, [64..127] col targets
    __shared__ float sgm[64 * 65];    // row-masked sigmoid tile, padded stride 65
    __shared__ int   slast[2];        // last_r, last_c
    __shared__ float wred[8];

    const int t = threadIdx.x;
    const int b = blockIdx.x;
    const float4* gb  = reinterpret_cast<const float4*>(grid)  + (size_t)b * 1024;
    const float4* hb  = reinterpret_cast<const float4*>(hints) + (size_t)b * 512;
    const float4* wgv = reinterpret_cast<const float4*>(wg);
    const float4* whv = reinterpret_cast<const float4*>(wh);

    if (t < 2) slast[t] = -1;

    // ---- Phase 1: hints. thread t<128 owns one (k,i) row of 16 values ----
    float s2p = 0.0f;
    if (t < 128) {
        float hs = 0.0f;
        #pragma unroll
        for (int k = 0; k < 4; ++k) {
            float4 h = hb[t * 4 + k];
            float4 w = whv[t * 4 + k];
            hs  += (h.x + h.y) + (h.z + h.w);
            s2p += h.x * w.x; s2p += h.y * w.y; s2p += h.z * w.z; s2p += h.w * w.w;
        }
        hsum[t] = hs;
    }
    __syncthreads();
    if (t < 128 && hsum[t] > 0.0f) atomicMax(&slast[t >> 6], t & 63);
    __syncthreads();

    int size;
    {
        int lr = slast[0], lc = slast[1];
        size = (lr >= 0 && lc >= 0) ? (max(lr, lc) + 1) : 12;
    }

    // ---- Phase 2: stream grid tile, fully coalesced float4 ----
    float s1p = 0.0f, binp = 0.0f, rerrp = 0.0f;
    #pragma unroll
    for (int k = 0; k < 4; ++k) {
        int idx = k * 256 + t;          // float4 index within 64x64 tile
        int r   = idx >> 4;             // row 0..63
        int c0  = (idx & 15) << 2;      // column start 0..60
        float4 g = gb[idx];
        float4 w = wgv[idx];
        s1p += g.x * w.x; s1p += g.y * w.y; s1p += g.z * w.z; s1p += g.w * w.w;

        float rm = (r < size) ? 1.0f : 0.0f;
        float gx[4] = {g.x, g.y, g.z, g.w};
        float pr = 0.0f;
        #pragma unroll
        for (int e = 0; e < 4; ++e) {
            float x  = gx[e];
            float sg = __fdividef(1.0f, 1.0f + __expf(-3.0f * x));
            if (c0 + e < size) {        // column mask m[j]
                pr   += sg;
                binp += x * x * rm;     // both masks for binary term
            }
            sgm[r * 65 + c0 + e] = sg * rm;  // row mask baked in for column sums
        }
        // actual_rows[r]: reduce over the 16 lanes covering row r
        pr += __shfl_xor_sync(0xffffffffu, pr, 1);
        pr += __shfl_xor_sync(0xffffffffu, pr, 2);
        pr += __shfl_xor_sync(0xffffffffu, pr, 4);
        pr += __shfl_xor_sync(0xffffffffu, pr, 8);
        if ((t & 15) == 0 && r < size) {
            float d = pr - hsum[r];
            rerrp += d * d;
        }
    }
    __syncthreads();

    // ---- Phase 3: column sums (conflict-free via 65-stride padding) ----
    float cerrp = 0.0f;
    if (t < 64) {
        float ac = 0.0f;
        #pragma unroll
        for (int i = 0; i < 64; ++i) ac += sgm[i * 65 + t];
        if (t < size) {
            float d = ac - hsum[64 + t];
            cerrp = d * d;
        }
    }

    // ---- Combine per-batch energy ----
    float inv   = __fdividef(1.0f, (float)size);
    float local = s1p + s2p
                + 10.0f * inv * (rerrp + cerrp)
                + 0.1f  * inv * inv * binp;

    // ---- Block reduction, then one global atomic per CTA ----
    #pragma unroll
    for (int o = 16; o > 0; o >>= 1)
        local += __shfl_down_sync(0xffffffffu, local, o);
    if ((t & 31) == 0) wred[t >> 5] = local;
    __syncthreads();
    if (t < 32) {
        float v = (t < 8) ? wred[t] : 0.0f;
        #pragma unroll
        for (int o = 4; o > 0; o >>= 1)
            v += __shfl_down_sync(0xffffffffu, v, o);
        if (t == 0) atomicAdd(out, v * (1.0f / 4096.0f));
    }
}

extern "C" void kernel_launch(void* const* d_in, const int* in_sizes, int n_in,
                              void* d_out, int out_size) {
    const float* grid  = (const float*)d_in[0];
    const float* hints = (const float*)d_in[1];
    const float* wg    = (const float*)d_in[2];
    const float* wh    = (const float*)d_in[3];
    float* out = (float*)d_out;

    zero_kernel<<<1, 1>>>(out);
    energy_kernel<<<4096, 256>>>(grid, hints, wg, wh, out);
}

// round 3
// speedup vs baseline: 1.0232x; 1.0232x over previous
#include <cuda_runtime.h>

// B=4096, N=64, H=16, FALLBACK=12
// grid (B,1,64,64) f32 | hints (B,2,64,16) f32 | w_g (1,64,64) | w_h (2,64,16)

static __global__ void zero_kernel(float* out) { out[0] = 0.0f; }

#define BPC 2  // batches per CTA

__global__ void __launch_bounds__(256) energy_kernel(
    const float* __restrict__ grid, const float* __restrict__ hints,
    const float* __restrict__ wg,   const float* __restrict__ wh,
    float* __restrict__ out)
{
    __shared__ float hsum[128];        // [0..63] row targets, [64..127] col targets
    __shared__ float colp[16 * 64];    // per-rowgroup column partials
    __shared__ int   slast[2];
    __shared__ float wred[8];

    const int t = threadIdx.x;
    const int rg = t >> 4;             // row-group 0..15
    const int c0 = (t & 15) << 2;      // owned column start

    // Preload w_g into registers: reused across BPC batches.
    const float4* wgv = reinterpret_cast<const float4*>(wg);
    float4 wgr[4];
    #pragma unroll
    for (int k = 0; k < 4; ++k) wgr[k] = wgv[k * 256 + t];

    const float4* whv = reinterpret_cast<const float4*>(wh);

    float acc = 0.0f;  // per-thread energy accumulator over batches

    #pragma unroll
    for (int j = 0; j < BPC; ++j) {
        const int b = blockIdx.x * BPC + j;
        const float4* gb = reinterpret_cast<const float4*>(grid)  + (size_t)b * 1024;
        const float4* hb = reinterpret_cast<const float4*>(hints) + (size_t)b * 512;

        __syncthreads();               // colp/hsum/slast safe to reuse
        if (t < 2) slast[t] = -1;

        // ---- Phase 1: hints (t<128: one (k,i) row of 16) ----
        float s2p = 0.0f;
        if (t < 128) {
            float hs = 0.0f;
            #pragma unroll
            for (int k = 0; k < 4; ++k) {
                float4 h = hb[t * 4 + k];
                float4 w = whv[t * 4 + k];
                hs  += (h.x + h.y) + (h.z + h.w);
                s2p += h.x * w.x; s2p += h.y * w.y; s2p += h.z * w.z; s2p += h.w * w.w;
            }
            hsum[t] = hs;
        }
        __syncthreads();
        if (t < 128 && hsum[t] > 0.0f) atomicMax(&slast[t >> 6], t & 63);
        __syncthreads();

        int size;
        {
            int lr = slast[0], lc = slast[1];
            size = (lr >= 0 && lc >= 0) ? (max(lr, lc) + 1) : 12;
        }

        // ---- Phase 2: stream grid; row sums via shfl, col partials in regs ----
        float s1p = 0.0f, binp = 0.0f, rerrp = 0.0f;
        float pc0 = 0.0f, pc1 = 0.0f, pc2 = 0.0f, pc3 = 0.0f;
        #pragma unroll
        for (int k = 0; k < 4; ++k) {
            int r = k * 16 + rg;
            float4 g = gb[k * 256 + t];
            float4 w = wgr[k];
            s1p += g.x * w.x; s1p += g.y * w.y; s1p += g.z * w.z; s1p += g.w * w.w;

            float rm = (r < size) ? 1.0f : 0.0f;
            float gx[4] = {g.x, g.y, g.z, g.w};
            float sg[4], pr = 0.0f;
            #pragma unroll
            for (int e = 0; e < 4; ++e) {
                float x = gx[e];
                sg[e] = __fdividef(1.0f, 1.0f + __expf(-3.0f * x)) * rm;
                if (c0 + e < size) {
                    pr   += sg[e];       // row-sum term (col mask, sg has rm but
                                         // pr only read when r<size so rm=1)
                    binp += x * x * rm;  // both masks
                }
            }
            pc0 += sg[0]; pc1 += sg[1]; pc2 += sg[2]; pc3 += sg[3];

            // actual_rows[r]: reduce across the 16 lanes of this row
            pr += __shfl_xor_sync(0xffffffffu, pr, 1);
            pr += __shfl_xor_sync(0xffffffffu, pr, 2);
            pr += __shfl_xor_sync(0xffffffffu, pr, 4);
            pr += __shfl_xor_sync(0xffffffffu, pr, 8);
            if ((t & 15) == 0 && r < size) {
                float d = pr - hsum[r];
                rerrp += d * d;
            }
        }

        // ---- Phase 3: column reduction (16 row-groups -> 64 columns) ----
        *reinterpret_cast<float4*>(&colp[rg * 64 + c0]) =
            make_float4(pc0, pc1, pc2, pc3);
        __syncthreads();

        float cerrp = 0.0f;
        if (t < 64) {
            float ac = 0.0f;
            #pragma unroll
            for (int g2 = 0; g2 < 16; ++g2) ac += colp[g2 * 64 + t];
            if (t < size) {
                float d = ac - hsum[64 + t];
                cerrp = d * d;
            }
        }

        float inv = __fdividef(1.0f, (float)size);
        acc += s1p + s2p
             + 10.0f * inv * (rerrp + cerrp)
             + 0.1f  * inv * inv * binp;
    }

    // ---- Block reduction, one atomic per CTA ----
    #pragma unroll
    for (int o = 16; o > 0; o >>= 1)
        acc += __shfl_down_sync(0xffffffffu, acc, o);
    if ((t & 31) == 0) wred[t >> 5] = acc;
    __syncthreads();
    if (t < 32) {
        float v = (t < 8) ? wred[t] : 0.0f;
        #pragma unroll
        for (int o = 4; o > 0; o >>= 1)
            v += __shfl_down_sync(0xffffffffu, v, o);
        if (t == 0) atomicAdd(out, v * (1.0f / 4096.0f));
    }
}

extern "C" void kernel_launch(void* const* d_in, const int* in_sizes, int n_in,
                              void* d_out, int out_size) {
    const float* grid  = (const float*)d_in[0];
    const float* hints = (const float*)d_in[1];
    const float* wg    = (const float*)d_in[2];
    const float* wh    = (const float*)d_in[3];
    float* out = (float*)d_out;

    zero_kernel<<<1, 1>>>(out);
    energy_kernel<<<4096 / BPC, 256>>>(grid, hints, wg, wh, out);
}

// round 4
// speedup vs baseline: 1.1841x; 1.1573x over previous
#include <cuda_runtime.h>

// B=4096, N=64, H=16, FALLBACK=12
// grid (B,1,64,64) f32 | hints (B,2,64,16) f32 | w_g (1,64,64) | w_h (2,64,16)

__device__ int g_ctr;

static __global__ void zero_kernel(float* out) { out[0] = 0.0f; g_ctr = 0; }

#define NB 4096
#define NCTA 1184

__global__ void __launch_bounds__(256, 6) energy_kernel(
    const float* __restrict__ grid, const float* __restrict__ hints,
    const float* __restrict__ wg,   const float* __restrict__ wh,
    float* __restrict__ out)
{
    __shared__ float wgs[4096];     // w_g tile, 16KB
    __shared__ float whs[2048];     // w_h,     8KB
    __shared__ float hsum[128];     // row/col targets
    __shared__ float colp[1024];    // 16 rowgroups x 64 col partials
    __shared__ int   slast[2];
    __shared__ float wred[8];
    __shared__ int   snext;

    const int t  = threadIdx.x;
    const int rg = t >> 4;          // row-group 0..15
    const int c0 = (t & 15) << 2;   // owned column start
    const int p  = t >> 1;          // hint row 0..127 (2 threads per row)

    if (t == 0) snext = atomicAdd(&g_ctr, 1);
    if (t < 2)  slast[t] = -1;

    // One-time weight preload into shared
    {
        const float4* wgv = reinterpret_cast<const float4*>(wg);
        const float4* whv = reinterpret_cast<const float4*>(wh);
        float4* wgs4 = reinterpret_cast<float4*>(wgs);
        float4* whs4 = reinterpret_cast<float4*>(whs);
        #pragma unroll
        for (int k = 0; k < 4; ++k) wgs4[k * 256 + t] = wgv[k * 256 + t];
        #pragma unroll
        for (int k = 0; k < 2; ++k) whs4[k * 256 + t] = whv[k * 256 + t];
    }
    __syncthreads();

    int b = snext;
    if (b >= NB) return;            // uniform across CTA

    const float4* wgs4 = reinterpret_cast<const float4*>(wgs);
    const float4* whs4 = reinterpret_cast<const float4*>(whs);
    float acc = 0.0f;

    while (true) {
        const float4* gb = reinterpret_cast<const float4*>(grid)  + (size_t)b * 1024;
        const float4* hb = reinterpret_cast<const float4*>(hints) + (size_t)b * 512;

        // ---- Phase 1: hints. 2 threads per row, 2 float4 each ----
        float s2p = 0.0f, hs;
        {
            float4 h0 = hb[2 * t], h1 = hb[2 * t + 1];
            float4 w0 = whs4[2 * t], w1 = whs4[2 * t + 1];
            hs   = (h0.x + h0.y) + (h0.z + h0.w) + (h1.x + h1.y) + (h1.z + h1.w);
            s2p += h0.x * w0.x; s2p += h0.y * w0.y; s2p += h0.z * w0.z; s2p += h0.w * w0.w;
            s2p += h1.x * w1.x; s2p += h1.y * w1.y; s2p += h1.z * w1.z; s2p += h1.w * w1.w;
        }
        float hsfull = hs + __shfl_xor_sync(0xffffffffu, hs, 1);
        if ((t & 1) == 0) {
            hsum[p] = hsfull;
            if (hsfull > 0.0f) atomicMax(&slast[p >> 6], p & 63);
        }
        __syncthreads();    // A: hsum/slast ready

        int size;
        {
            int lr = slast[0], lc = slast[1];
            size = (lr >= 0 && lc >= 0) ? (max(lr, lc) + 1) : 12;
        }

        // ---- Phase 2: stream grid; row sums via shfl, col partials in regs ----
        float s1p = 0.0f, binp = 0.0f, rerrp = 0.0f;
        float pc0 = 0.0f, pc1 = 0.0f, pc2 = 0.0f, pc3 = 0.0f;
        #pragma unroll
        for (int k = 0; k < 4; ++k) {
            int r = k * 16 + rg;
            float4 g = gb[k * 256 + t];
            float4 w = wgs4[k * 256 + t];
            s1p += g.x * w.x; s1p += g.y * w.y; s1p += g.z * w.z; s1p += g.w * w.w;

            float rm = (r < size) ? 1.0f : 0.0f;
            float gx[4] = {g.x, g.y, g.z, g.w};
            float sg[4], pr = 0.0f;
            #pragma unroll
            for (int e = 0; e < 4; ++e) {
                float x = gx[e];
                sg[e] = __fdividef(1.0f, 1.0f + __expf(-3.0f * x)) * rm;
                if (c0 + e < size) {
                    pr   += sg[e];
                    binp += x * x * rm;
                }
            }
            pc0 += sg[0]; pc1 += sg[1]; pc2 += sg[2]; pc3 += sg[3];

            pr += __shfl_xor_sync(0xffffffffu, pr, 1);
            pr += __shfl_xor_sync(0xffffffffu, pr, 2);
            pr += __shfl_xor_sync(0xffffffffu, pr, 4);
            pr += __shfl_xor_sync(0xffffffffu, pr, 8);
            if ((t & 15) == 0 && r < size) {
                float d = pr - hsum[r];
                rerrp += d * d;
            }
        }
        *reinterpret_cast<float4*>(&colp[rg * 64 + c0]) =
            make_float4(pc0, pc1, pc2, pc3);
        if (t == 0) snext = atomicAdd(&g_ctr, 1);   // overlapped steal
        __syncthreads();    // B: colp + snext ready

        // ---- Phase 3: column reduction + per-batch energy ----
        float cerrp = 0.0f;
        if (t < 64) {
            float ac = 0.0f;
            #pragma unroll
            for (int g2 = 0; g2 < 16; ++g2) ac += colp[g2 * 64 + t];
            if (t < size) {
                float d = ac - hsum[64 + t];
                cerrp = d * d;
            }
        }
        if (t < 2) slast[t] = -1;   // reset for next batch (reads done pre-B)

        float inv = __fdividef(1.0f, (float)size);
        acc += s1p + s2p
             + 10.0f * inv * (rerrp + cerrp)
             + 0.1f  * inv * inv * binp;

        b = snext;
        if (b >= NB) break;
        __syncthreads();    // C: phase-3 reads done before next batch writes
    }

    // ---- Block reduction, one atomic per CTA ----
    #pragma unroll
    for (int o = 16; o > 0; o >>= 1)
        acc += __shfl_down_sync(0xffffffffu, acc, o);
    if ((t & 31) == 0) wred[t >> 5] = acc;
    __syncthreads();
    if (t < 32) {
        float v = (t < 8) ? wred[t] : 0.0f;
        #pragma unroll
        for (int o = 4; o > 0; o >>= 1)
            v += __shfl_down_sync(0xffffffffu, v, o);
        if (t == 0) atomicAdd(out, v * (1.0f / (float)NB));
    }
}

extern "C" void kernel_launch(void* const* d_in, const int* in_sizes, int n_in,
                              void* d_out, int out_size) {
    const float* grid  = (const float*)d_in[0];
    const float* hints = (const float*)d_in[1];
    const float* wg    = (const float*)d_in[2];
    const float* wh    = (const float*)d_in[3];
    float* out = (float*)d_out;

    zero_kernel<<<1, 1>>>(out);
    energy_kernel<<<NCTA, 256>>>(grid, hints, wg, wh, out);
}